// round 13
// baseline (speedup 1.0000x reference)
#include <cuda_runtime.h>
#include <math.h>
#include <stdint.h>

// ---------------- static config ----------------
constexpr int HH = 376;
constexpr int WW = 376;
constexpr int HWSZ = HH * WW;      // 141376
constexpr int TOPK = 500;

// ---------------- device scratch (no allocs allowed) ----------------
__device__ float g_shared[64 * HWSZ];        // shared_conv output
__device__ float g_h0[64 * HWSZ];            // hm branch hidden
__device__ float g_hm[3 * HWSZ];             // sigmoid scores
__device__ float g_wshT[256 * 9 * 64];       // W_sh transposed [ci][tap][oc]
__device__ float g_w1hmT[64 * 9 * 64];       // W1s[0] transposed
__device__ float g_w1bT[5 * 64 * 9 * 64];    // W1s[1..5] transposed
__device__ float g_w2hmT[64 * 9 * 3];        // W2s[0] transposed [ci][tap][oc]
__device__ unsigned int g_histC[1024];       // coarse (bits>>22)
__device__ unsigned int g_histF[1024];       // fine within coarse bin
__device__ unsigned int g_coarseSel;
__device__ unsigned int g_aboveC;
__device__ unsigned int g_thresh;
__device__ int g_candCount;
__device__ unsigned long long g_cand[4096];
__device__ float g_topk_score[512];
__device__ int g_topk_sp[512];
__device__ int g_topk_cls[512];
__device__ float g_sparse[5 * 512 * 3];

// ---------------- packed fp32x2 helpers ----------------
__device__ __forceinline__ void ffma2(unsigned long long& d, unsigned long long a,
                                      unsigned long long b) {
    asm("fma.rn.f32x2 %0, %1, %2, %0;" : "+l"(d) : "l"(a), "l"(b));
}
__device__ __forceinline__ void unpack2(unsigned long long v, float& lo, float& hi) {
    asm("mov.b64 {%0, %1}, %2;" : "=f"(lo), "=f"(hi) : "l"(v));
}
__device__ __forceinline__ uint32_t smem_u32(const void* p) {
    uint32_t a;
    asm("{ .reg .u64 t; cvta.to.shared.u64 t, %1; cvt.u32.u64 %0, t; }"
        : "=r"(a) : "l"(p));
    return a;
}

// ---------------- prep: weight transposes ----------------
__global__ void prep_kernel(const float* __restrict__ W_sh,
                            const float* __restrict__ W1s,
                            const float* __restrict__ W2s) {
    const int n1 = 256 * 576;           // 147456
    const int n2 = 64 * 576;            // 36864
    const int n3 = 5 * 64 * 576;        // 184320
    const int n4 = 64 * 27;             // 1728
    const int total = n1 + n2 + n3 + n4;
    for (int i = blockIdx.x * blockDim.x + threadIdx.x; i < total;
         i += gridDim.x * blockDim.x) {
        if (i < n1) {
            int c = i / 576, r = i % 576, t = r / 64, o = r % 64;
            g_wshT[i] = W_sh[(o * 256 + c) * 9 + t];
        } else if (i < n1 + n2) {
            int j = i - n1;
            int c = j / 576, t = (j % 576) / 64, o = j % 64;
            g_w1hmT[j] = W1s[(o * 64 + c) * 9 + t];
        } else if (i < n1 + n2 + n3) {
            int j = i - n1 - n2;
            int br = j / 36864, k = j % 36864;
            int c = k / 576, t = (k % 576) / 64, o = k % 64;
            g_w1bT[j] = W1s[(((br + 1) * 64 + o) * 64 + c) * 9 + t];
        } else {
            int j = i - n1 - n2 - n3;
            int c = j / 27, t = (j % 27) / 3, o = j % 3;
            g_w2hmT[j] = W2s[(o * 64 + c) * 9 + t];
        }
    }
}

__global__ void memset_kernel() {
    int tid = threadIdx.x;
    if (tid < 1024) {
        g_histC[tid] = 0u;
        g_histF[tid] = 0u;
    }
    if (tid == 0) g_candCount = 0;
}

// ---------------- dense 3x3 conv + BN + ReLU (f32x2, dup-smem layout) ------
// tile: 64 oc x (64x, 2y) pixels; 256 threads; thread = 8 oc x 4 px
// input smem holds each pixel DUPLICATED: LDS.128 -> two f32x2 broadcast ops.
// inputs: LDG->reg->STS.64 pipeline; weights: cp.async double buffer.
constexpr int DUP_F = 8 * 528;     // floats per dup input buffer (8ch*4row*132)
constexpr int SW_F = 8 * 576;      // floats per weight buffer
constexpr int DYN_SMEM = (2 * DUP_F + 2 * SW_F) * 4;   // 70656 bytes

template <int CIN>
__global__ void __launch_bounds__(256, 3)
conv3x3_bn_relu(const float* __restrict__ in, const float* __restrict__ wT,
                const float* __restrict__ bnp, float* __restrict__ out) {
    extern __shared__ char dynsm[];
    float* s_dup0 = (float*)dynsm;                      // [2][DUP_F]
    float* s_w0 = (float*)(dynsm + 2 * DUP_F * 4);      // [2][SW_F]
    __shared__ float s_scale[64], s_shift[64];

    int tid = threadIdx.x;
    if (tid < 64) {
        float g = bnp[tid], b = bnp[64 + tid], m = bnp[128 + tid], v = bnp[192 + tid];
        float sc = g * rsqrtf(v + 1e-5f);
        s_scale[tid] = sc;
        s_shift[tid] = b - m * sc;
    }
    const int bx = blockIdx.x * 64, by = blockIdx.y * 2;
    const int lg = tid & 31;
    const int gx4 = (lg & 15) << 2;   // 0..60
    const int ty = lg >> 4;           // 0..1
    const int ob = tid >> 5;          // 0..7

    // precompute staging slots once: thread covers slots i = tid + s*256, i<2112
    int src[9];       // gmem offset within channel group (or -1 OOB, -2 unused)
    int ddst[9];      // dup-buffer float offset
#pragma unroll
    for (int s = 0; s < 9; ++s) {
        int i = tid + s * 256;
        if (i < 2112) {
            int c = i / 264, r = (i % 264) / 66, xx = i % 66;
            int gy = by + r - 1, gx = bx + xx - 1;
            ddst[s] = c * 528 + r * 132 + xx * 2;
            src[s] = ((unsigned)gy < (unsigned)HH && (unsigned)gx < (unsigned)WW)
                         ? (c * HWSZ + gy * WW + gx) : -1;
        } else {
            ddst[s] = -1; src[s] = -2;
        }
    }

    const uint32_t w_base = smem_u32(s_w0);
    auto stage_w = [&](int cc, int b) {
        const float4* wsrc = (const float4*)(wT + cc * 8 * 576);
        uint32_t woff = w_base + (uint32_t)(b * SW_F * 4);
#pragma unroll
        for (int s = 0; s < 5; ++s) {
            int idx = tid + s * 256;
            if (idx < 1152) {
                asm volatile("cp.async.cg.shared.global [%0], [%1], 16;"
                             :: "r"(woff + idx * 16), "l"(wsrc + idx));
            }
        }
        asm volatile("cp.async.commit_group;" ::: "memory");
    };

    float rin[9];
    auto ldg_in = [&](int cc) {
        const float* ibase = in + cc * 8 * HWSZ;
#pragma unroll
        for (int s = 0; s < 9; ++s) {
            if (src[s] != -2)
                rin[s] = (src[s] >= 0) ? __ldg(ibase + src[s]) : 0.f;
        }
    };
    auto sts_dup = [&](int b) {
        float* dbuf = s_dup0 + b * DUP_F;
#pragma unroll
        for (int s = 0; s < 9; ++s) {
            if (src[s] != -2) {
                float v = rin[s];
                *(float2*)(dbuf + ddst[s]) = make_float2(v, v);
            }
        }
    };

    unsigned long long acc2[4][4];
#pragma unroll
    for (int o = 0; o < 4; ++o)
#pragma unroll
        for (int j = 0; j < 4; ++j) acc2[o][j] = 0ull;

    constexpr int NCHUNK = CIN / 8;
    // prologue
    stage_w(0, 0);
    ldg_in(0);
    sts_dup(0);
    ldg_in(1);
    asm volatile("cp.async.wait_group 0;" ::: "memory");
    __syncthreads();
    stage_w(1, 1);

    for (int ci = 0; ci < NCHUNK; ++ci) {
        const float* s_dup = s_dup0 + (ci & 1) * DUP_F;
        const float* s_w = s_w0 + (ci & 1) * SW_F;
#pragma unroll
        for (int cl = 0; cl < 8; ++cl) {
#pragma unroll
            for (int dy = 0; dy < 3; ++dy) {
                const float* rowp = &s_dup[cl * 528 + (ty + dy) * 132 + gx4 * 2];
                unsigned long long riv[6];
                {
                    ulonglong2 p0 = *(const ulonglong2*)(rowp);
                    ulonglong2 p1 = *(const ulonglong2*)(rowp + 4);
                    ulonglong2 p2 = *(const ulonglong2*)(rowp + 8);
                    riv[0] = p0.x; riv[1] = p0.y;
                    riv[2] = p1.x; riv[3] = p1.y;
                    riv[4] = p2.x; riv[5] = p2.y;
                }
#pragma unroll
                for (int dx = 0; dx < 3; ++dx) {
                    const unsigned long long* wp = (const unsigned long long*)
                        &s_w[cl * 576 + (dy * 3 + dx) * 64 + (ob << 3)];
                    unsigned long long w0 = wp[0], w1 = wp[1], w2 = wp[2], w3 = wp[3];
#pragma unroll
                    for (int j = 0; j < 4; ++j) {
                        unsigned long long iv = riv[j + dx];
                        ffma2(acc2[0][j], w0, iv);
                        ffma2(acc2[1][j], w1, iv);
                        ffma2(acc2[2][j], w2, iv);
                        ffma2(acc2[3][j], w3, iv);
                    }
                }
            }
        }
        if (ci + 1 < NCHUNK) {
            sts_dup((ci + 1) & 1);
            asm volatile("cp.async.wait_group 0;" ::: "memory");
            __syncthreads();
            if (ci + 2 < NCHUNK) {
                ldg_in(ci + 2);
                stage_w(ci + 2, ci & 1);
            }
        }
    }

    int oy = by + ty;
    if (oy < HH) {
#pragma unroll
        for (int op = 0; op < 4; ++op) {
#pragma unroll
            for (int h = 0; h < 2; ++h) {
                int oc = (ob << 3) + op * 2 + h;
                float sc = s_scale[oc], sh = s_shift[oc];
                int base = oc * HWSZ + oy * WW + bx + gx4;
#pragma unroll
                for (int j = 0; j < 4; ++j) {
                    int ox = bx + gx4 + j;
                    if (ox < WW) {
                        float lo, hi;
                        unpack2(acc2[op][j], lo, hi);
                        float a = h ? hi : lo;
                        out[base + j] = fmaxf(fmaf(a, sc, sh), 0.f);
                    }
                }
            }
        }
    }
}

// ---------------- hm final conv (64->3) + bias + sigmoid ----------------
__global__ void __launch_bounds__(128)
conv_hm_final(const float* __restrict__ h, const float* __restrict__ b2s) {
    __shared__ float s_in[16][3][132];
    __shared__ float s_w[64 * 27];
    int tid = threadIdx.x;
    int bx = blockIdx.x * 128, y = blockIdx.y;
    for (int i = tid; i < 1728; i += 128) s_w[i] = g_w2hmT[i];
    float acc0 = 0.f, acc1 = 0.f, acc2 = 0.f;
    for (int cc = 0; cc < 64; cc += 16) {
        __syncthreads();
        for (int i = tid; i < 16 * 3 * 130; i += 128) {
            int c = i / 390, r = (i / 130) % 3, xx = i % 130;
            int gy = y + r - 1, gx = bx + xx - 1;
            float v = 0.f;
            if ((unsigned)gy < (unsigned)HH && (unsigned)gx < (unsigned)WW)
                v = h[(cc + c) * HWSZ + gy * WW + gx];
            s_in[c][r][xx] = v;
        }
        __syncthreads();
#pragma unroll
        for (int cl = 0; cl < 16; ++cl) {
#pragma unroll
            for (int dy = 0; dy < 3; ++dy)
#pragma unroll
                for (int dx = 0; dx < 3; ++dx) {
                    float iv = s_in[cl][dy][tid + dx];
                    const float* wp = &s_w[(cc + cl) * 27 + (dy * 3 + dx) * 3];
                    acc0 = fmaf(wp[0], iv, acc0);
                    acc1 = fmaf(wp[1], iv, acc1);
                    acc2 = fmaf(wp[2], iv, acc2);
                }
        }
    }
    int ox = bx + tid;
    if (ox < WW) {
        float v0 = acc0 + b2s[0], v1 = acc1 + b2s[1], v2 = acc2 + b2s[2];
        g_hm[0 * HWSZ + y * WW + ox] = 1.f / (1.f + expf(-v0));
        g_hm[1 * HWSZ + y * WW + ox] = 1.f / (1.f + expf(-v1));
        g_hm[2 * HWSZ + y * WW + ox] = 1.f / (1.f + expf(-v2));
    }
}

// ---------------- top-k: privatized histograms / scans / collect / sort ----
__global__ void __launch_bounds__(1024) histA_kernel() {
    __shared__ unsigned sh[1024];
    int tid = threadIdx.x;
    sh[tid] = 0u;
    __syncthreads();
    int n = 3 * HWSZ;
    for (int i = blockIdx.x * blockDim.x + tid; i < n;
         i += gridDim.x * blockDim.x) {
        unsigned bits = __float_as_uint(g_hm[i]);
        atomicAdd(&sh[bits >> 22], 1u);
    }
    __syncthreads();
    unsigned v = sh[tid];
    if (v) atomicAdd(&g_histC[tid], v);
}

__global__ void scanA_kernel() {
    __shared__ unsigned s[1024];
    int tid = threadIdx.x;
    s[tid] = g_histC[tid];
    __syncthreads();
    if (tid == 0) {
        unsigned cum = 0;
        unsigned bc = 0, above = 0;
        for (int b = 1023; b >= 0; --b) {
            unsigned nc = cum + s[b];
            if (nc >= TOPK) { bc = (unsigned)b; above = cum; break; }
            cum = nc;
        }
        g_coarseSel = bc;
        g_aboveC = above;
    }
}

__global__ void __launch_bounds__(1024) histB_kernel() {
    __shared__ unsigned sh[1024];
    int tid = threadIdx.x;
    sh[tid] = 0u;
    __syncthreads();
    unsigned cb = g_coarseSel;
    int n = 3 * HWSZ;
    for (int i = blockIdx.x * blockDim.x + tid; i < n;
         i += gridDim.x * blockDim.x) {
        unsigned bits = __float_as_uint(g_hm[i]);
        if ((bits >> 22) == cb) atomicAdd(&sh[(bits >> 12) & 1023], 1u);
    }
    __syncthreads();
    unsigned v = sh[tid];
    if (v) atomicAdd(&g_histF[tid], v);
}

__global__ void scanB_kernel() {
    __shared__ unsigned s[1024];
    int tid = threadIdx.x;
    s[tid] = g_histF[tid];
    __syncthreads();
    if (tid == 0) {
        unsigned cb = g_coarseSel;
        unsigned cum = g_aboveC;
        unsigned th = 0;
        for (int t = 1023; t >= 0; --t) {
            cum += s[t];
            if (cum >= TOPK) { th = ((cb << 10) + (unsigned)t) << 12; break; }
        }
        g_thresh = th;
    }
}

__global__ void collect_kernel() {
    int n = 3 * HWSZ;
    unsigned th = g_thresh;
    for (int i = blockIdx.x * blockDim.x + threadIdx.x; i < n;
         i += gridDim.x * blockDim.x) {
        unsigned bits = __float_as_uint(g_hm[i]);
        if (bits >= th) {
            int slot = atomicAdd(&g_candCount, 1);
            if (slot < 4096)
                g_cand[slot] = ((unsigned long long)bits << 32) |
                               (unsigned)(0xFFFFFFFFu - (unsigned)i);
        }
    }
}

__global__ void __launch_bounds__(1024) sort_kernel() {
    __shared__ unsigned long long ks[4096];
    int tid = threadIdx.x;
    int n = g_candCount;
    if (n > 4096) n = 4096;
    for (int i = tid; i < 4096; i += 1024) ks[i] = (i < n) ? g_cand[i] : 0ull;
    __syncthreads();
    for (int k = 2; k <= 4096; k <<= 1) {
        for (int j = k >> 1; j > 0; j >>= 1) {
            for (int i = tid; i < 4096; i += 1024) {
                int ixj = i ^ j;
                if (ixj > i) {
                    bool up = ((i & k) == 0);
                    unsigned long long a = ks[i], b = ks[ixj];
                    if ((a > b) == up) { ks[i] = b; ks[ixj] = a; }
                }
            }
            __syncthreads();
        }
    }
    if (tid < TOPK) {
        unsigned long long key = ks[4095 - tid];
        unsigned bits = (unsigned)(key >> 32);
        unsigned idx = 0xFFFFFFFFu - (unsigned)(key & 0xFFFFFFFFu);
        g_topk_score[tid] = __uint_as_float(bits);
        int cls = idx / HWSZ;
        int sp = idx - cls * HWSZ;
        g_topk_cls[tid] = cls;
        g_topk_sp[tid] = sp;
    }
}

// ---------------- sparse branch eval at top-k positions ----------------
__global__ void __launch_bounds__(256)
sparse_kernel(const float* __restrict__ bn1s, const float* __restrict__ W2s,
              const float* __restrict__ b2s) {
    __shared__ float smem[6400 + 4608 + 128];
    __shared__ int s_cx[4], s_cy[4];
    float* s_patch = smem;              // [4][64][25]
    float* s_w = smem + 6400;           // [8][9][64]  (reused as s_h [4][9][64])
    float* s_bn = smem + 6400 + 4608;   // scale[64], shift[64]
    float* s_h = s_w;

    int tid = threadIdx.x;
    int bi = blockIdx.y;        // 0..4 -> branch bi+1
    int pg = blockIdx.x;        // 0..124
    int pos = tid >> 6, oc = tid & 63;

    if (tid < 4) {
        int sp = g_topk_sp[pg * 4 + tid];
        s_cy[tid] = sp / WW;
        s_cx[tid] = sp % WW;
    }
    if (tid < 64) {
        const float* bp = bn1s + (bi + 1) * 256;
        float g = bp[tid], b = bp[64 + tid], m = bp[128 + tid], v = bp[192 + tid];
        float sc = g * rsqrtf(v + 1e-5f);
        s_bn[tid] = sc;
        s_bn[64 + tid] = b - m * sc;
    }
    __syncthreads();
    for (int i = tid; i < 6400; i += 256) {
        int p = i / 1600, rem = i % 1600;
        int c = rem / 25, rc = rem % 25, dy = rc / 5, dx = rc % 5;
        int gy = s_cy[p] + dy - 2, gx = s_cx[p] + dx - 2;
        float v = 0.f;
        if ((unsigned)gy < (unsigned)HH && (unsigned)gx < (unsigned)WW)
            v = g_shared[c * HWSZ + gy * WW + gx];
        s_patch[i] = v;
    }

    float acc[9];
#pragma unroll
    for (int q = 0; q < 9; ++q) acc[q] = 0.f;

    const float* wsrc = g_w1bT + bi * 36864;
    for (int cc = 0; cc < 64; cc += 8) {
        __syncthreads();
        for (int i = tid; i < 4608; i += 256) s_w[i] = wsrc[cc * 576 + i];
        __syncthreads();
#pragma unroll
        for (int cl = 0; cl < 8; ++cl) {
            float pv[25];
            int base = pos * 1600 + (cc + cl) * 25;
#pragma unroll
            for (int q = 0; q < 25; ++q) pv[q] = s_patch[base + q];
#pragma unroll
            for (int dy = 0; dy < 3; ++dy)
#pragma unroll
                for (int dx = 0; dx < 3; ++dx) {
                    float w = s_w[cl * 576 + (dy * 3 + dx) * 64 + oc];
#pragma unroll
                    for (int py = 0; py < 3; ++py)
#pragma unroll
                        for (int px = 0; px < 3; ++px)
                            acc[py * 3 + px] =
                                fmaf(w, pv[(py + dy) * 5 + (px + dx)], acc[py * 3 + px]);
                }
        }
    }
    __syncthreads();
    float sc = s_bn[oc], sh = s_bn[64 + oc];
#pragma unroll
    for (int px = 0; px < 9; ++px) {
        int py = px / 3, pxx = px % 3;
        int gy = s_cy[pos] + py - 1, gx = s_cx[pos] + pxx - 1;
        float hv = 0.f;
        if ((unsigned)gy < (unsigned)HH && (unsigned)gx < (unsigned)WW)
            hv = fmaxf(fmaf(acc[px], sc, sh), 0.f);
        s_h[(pos * 9 + px) * 64 + oc] = hv;
    }
    __syncthreads();
    int wid = tid >> 5, lane = tid & 31;
    for (int t = wid; t < 12; t += 8) {
        int p = t / 3, o2 = t % 3;
        const float* w2 = W2s + (((bi + 1) * 3 + o2) * 64) * 9;
        float sum = 0.f;
        for (int i = lane; i < 576; i += 32) {
            int ic = i & 63, tp = i >> 6;
            sum = fmaf(s_h[(p * 9 + tp) * 64 + ic], w2[ic * 9 + tp], sum);
        }
#pragma unroll
        for (int off = 16; off > 0; off >>= 1)
            sum += __shfl_down_sync(0xffffffff, sum, off);
        if (lane == 0)
            g_sparse[(bi * 512 + pg * 4 + p) * 3 + o2] = sum + b2s[(bi + 1) * 3 + o2];
    }
}

// ---------------- decode ----------------
__global__ void decode_kernel(float* __restrict__ out) {
    int k = threadIdx.x;
    if (k >= TOPK) return;
    const float rect[3] = {0.68f, 0.71f, 0.65f};
    float s = g_topk_score[k];
    int cls = g_topk_cls[k];
    int sp = g_topk_sp[k];
    float ys = (float)(sp / WW);
    float xs = (float)(sp % WW);
    float c0 = g_sparse[(0 * 512 + k) * 3 + 0];
    float c1 = g_sparse[(0 * 512 + k) * 3 + 1];
    float cz = g_sparse[(1 * 512 + k) * 3 + 0];
    float d0 = expf(g_sparse[(2 * 512 + k) * 3 + 0]);
    float d1 = expf(g_sparse[(2 * 512 + k) * 3 + 1]);
    float d2 = expf(g_sparse[(2 * 512 + k) * 3 + 2]);
    float r0 = g_sparse[(3 * 512 + k) * 3 + 0];
    float r1 = g_sparse[(3 * 512 + k) * 3 + 1];
    float io = g_sparse[(4 * 512 + k) * 3 + 0];

    float xg = fmaf(xs + c0, 0.4f, -75.2f);
    float yg = fmaf(ys + c1, 0.4f, -75.2f);
    float heading = atan2f(r1, r0);
    io = fminf(fmaxf((io + 1.f) * 0.5f, 0.f), 1.f);
    float r = rect[cls];
    float sc = powf(s, 1.f - r) * powf(io, r);
    sc = (sc > 0.1f) ? sc : 0.f;

    out[k * 7 + 0] = xg;
    out[k * 7 + 1] = yg;
    out[k * 7 + 2] = cz;
    out[k * 7 + 3] = d0;
    out[k * 7 + 4] = d1;
    out[k * 7 + 5] = d2;
    out[k * 7 + 6] = heading;
    out[7 * TOPK + k] = sc;
    out[8 * TOPK + k] = (float)cls;
}

// ---------------- launch ----------------
extern "C" void kernel_launch(void* const* d_in, const int* in_sizes, int n_in,
                              void* d_out, int out_size) {
    const float* x = (const float*)d_in[0];
    const float* W_sh = (const float*)d_in[1];
    const float* bn_sh = (const float*)d_in[2];
    const float* W1s = (const float*)d_in[3];
    const float* bn1s = (const float*)d_in[4];
    const float* W2s = (const float*)d_in[5];
    const float* b2s = (const float*)d_in[6];
    float* out = (float*)d_out;

    float *p_shared, *p_h0, *p_wshT, *p_w1hmT;
    cudaGetSymbolAddress((void**)&p_shared, g_shared);
    cudaGetSymbolAddress((void**)&p_h0, g_h0);
    cudaGetSymbolAddress((void**)&p_wshT, g_wshT);
    cudaGetSymbolAddress((void**)&p_w1hmT, g_w1hmT);

    static bool attr_done = false;
    if (!attr_done) {
        cudaFuncSetAttribute(conv3x3_bn_relu<256>,
                             cudaFuncAttributeMaxDynamicSharedMemorySize, DYN_SMEM);
        cudaFuncSetAttribute(conv3x3_bn_relu<64>,
                             cudaFuncAttributeMaxDynamicSharedMemorySize, DYN_SMEM);
        attr_done = true;
    }

    prep_kernel<<<512, 256>>>(W_sh, W1s, W2s);
    memset_kernel<<<1, 1024>>>();

    dim3 cg((WW + 63) / 64, (HH + 1) / 2);
    conv3x3_bn_relu<256><<<cg, 256, DYN_SMEM>>>(x, p_wshT, bn_sh, p_shared);
    conv3x3_bn_relu<64><<<cg, 256, DYN_SMEM>>>(p_shared, p_w1hmT, bn1s, p_h0);

    dim3 hg((WW + 127) / 128, HH);
    conv_hm_final<<<hg, 128>>>(p_h0, b2s);

    histA_kernel<<<148, 1024>>>();
    scanA_kernel<<<1, 1024>>>();
    histB_kernel<<<148, 1024>>>();
    scanB_kernel<<<1, 1024>>>();
    collect_kernel<<<829, 512>>>();
    sort_kernel<<<1, 1024>>>();

    sparse_kernel<<<dim3(125, 5), 256>>>(bn1s, W2s, b2s);
    decode_kernel<<<1, 512>>>(out);
}

// round 15
// speedup vs baseline: 2.1100x; 2.1100x over previous
#include <cuda_runtime.h>
#include <math.h>
#include <stdint.h>

// ---------------- static config ----------------
constexpr int HH = 376;
constexpr int WW = 376;
constexpr int HWSZ = HH * WW;      // 141376
constexpr int TOPK = 500;

// ---------------- device scratch (no allocs allowed) ----------------
__device__ float g_shared[64 * HWSZ];        // shared_conv output
__device__ float g_h0[64 * HWSZ];            // hm branch hidden
__device__ float g_hm[3 * HWSZ];             // sigmoid scores
__device__ float g_wshT[256 * 9 * 64];       // W_sh transposed [ci][tap][oc]
__device__ float g_w1hmT[64 * 9 * 64];       // W1s[0] transposed
__device__ float g_w1bT[5 * 64 * 9 * 64];    // W1s[1..5] transposed
__device__ float g_w2hmT[64 * 9 * 3];        // W2s[0] transposed [ci][tap][oc]
__device__ unsigned int g_histC[1024];       // coarse (bits>>22)
__device__ unsigned int g_histF[1024];       // fine within coarse bin
__device__ unsigned int g_coarseSel;
__device__ unsigned int g_aboveC;
__device__ unsigned int g_thresh;
__device__ int g_candCount;
__device__ unsigned long long g_cand[4096];
__device__ float g_topk_score[512];
__device__ int g_topk_sp[512];
__device__ int g_topk_cls[512];
__device__ float g_sparse[5 * 512 * 3];

// ---------------- packed fp32x2 helpers ----------------
__device__ __forceinline__ void ffma2(unsigned long long& d, unsigned long long a,
                                      unsigned long long b) {
    asm("fma.rn.f32x2 %0, %1, %2, %0;" : "+l"(d) : "l"(a), "l"(b));
}
__device__ __forceinline__ unsigned long long packdup(float v) {
    unsigned long long d;
    asm("mov.b64 %0, {%1, %1};" : "=l"(d) : "f"(v));
    return d;
}
__device__ __forceinline__ void unpack2(unsigned long long v, float& lo, float& hi) {
    asm("mov.b64 {%0, %1}, %2;" : "=f"(lo), "=f"(hi) : "l"(v));
}
__device__ __forceinline__ uint32_t smem_u32(const void* p) {
    uint32_t a;
    asm("{ .reg .u64 t; cvta.to.shared.u64 t, %1; cvt.u32.u64 %0, t; }"
        : "=r"(a) : "l"(p));
    return a;
}

// ---------------- prep: weight transposes ----------------
__global__ void prep_kernel(const float* __restrict__ W_sh,
                            const float* __restrict__ W1s,
                            const float* __restrict__ W2s) {
    const int n1 = 256 * 576;           // 147456
    const int n2 = 64 * 576;            // 36864
    const int n3 = 5 * 64 * 576;        // 184320
    const int n4 = 64 * 27;             // 1728
    const int total = n1 + n2 + n3 + n4;
    for (int i = blockIdx.x * blockDim.x + threadIdx.x; i < total;
         i += gridDim.x * blockDim.x) {
        if (i < n1) {
            int c = i / 576, r = i % 576, t = r / 64, o = r % 64;
            g_wshT[i] = W_sh[(o * 256 + c) * 9 + t];
        } else if (i < n1 + n2) {
            int j = i - n1;
            int c = j / 576, t = (j % 576) / 64, o = j % 64;
            g_w1hmT[j] = W1s[(o * 64 + c) * 9 + t];
        } else if (i < n1 + n2 + n3) {
            int j = i - n1 - n2;
            int br = j / 36864, k = j % 36864;
            int c = k / 576, t = (k % 576) / 64, o = k % 64;
            g_w1bT[j] = W1s[(((br + 1) * 64 + o) * 64 + c) * 9 + t];
        } else {
            int j = i - n1 - n2 - n3;
            int c = j / 27, t = (j % 27) / 3, o = j % 3;
            g_w2hmT[j] = W2s[(o * 64 + c) * 9 + t];
        }
    }
}

__global__ void memset_kernel() {
    int tid = threadIdx.x;
    if (tid < 1024) {
        g_histC[tid] = 0u;
        g_histF[tid] = 0u;
    }
    if (tid == 0) g_candCount = 0;
}

// ---------------- dense 3x3 conv + BN + ReLU (f32x2 + cp.async pipeline) ----
// (reverted to round-12 version: plain smem layout, packdup in regs)
constexpr int SIN_F = 8 * 272;     // floats per input buffer
constexpr int SW_F = 8 * 576;      // floats per weight buffer
constexpr int DYN_SMEM = (2 * SIN_F + 2 * SW_F) * 4;   // 54272 bytes

template <int CIN>
__global__ void __launch_bounds__(256, 3)
conv3x3_bn_relu(const float* __restrict__ in, const float* __restrict__ wT,
                const float* __restrict__ bnp, float* __restrict__ out) {
    extern __shared__ char dynsm[];
    float* s_in0 = (float*)dynsm;                       // [2][SIN_F]
    float* s_w0 = (float*)(dynsm + 2 * SIN_F * 4);      // [2][SW_F]
    __shared__ float s_scale[64], s_shift[64];

    int tid = threadIdx.x;
    if (tid < 64) {
        float g = bnp[tid], b = bnp[64 + tid], m = bnp[128 + tid], v = bnp[192 + tid];
        float sc = g * rsqrtf(v + 1e-5f);
        s_scale[tid] = sc;
        s_shift[tid] = b - m * sc;
    }
    const int bx = blockIdx.x * 64, by = blockIdx.y * 2;
    const int lg = tid & 31;
    const int gx4 = (lg & 15) << 2;   // 0..60
    const int ty = lg >> 4;           // 0..1
    const int ob = tid >> 5;          // 0..7

    int src[9];
    uint32_t dstu[9];
    const uint32_t in_base = smem_u32(s_in0);
    const uint32_t w_base = smem_u32(s_w0);
#pragma unroll
    for (int s = 0; s < 9; ++s) {
        int i = tid + s * 256;
        if (i < 2112) {
            int c = i / 264, r = (i % 264) / 66, xx = i % 66;
            int gy = by + r - 1, gx = bx + xx - 1;
            dstu[s] = in_base + (c * 272 + r * 68 + xx) * 4;
            src[s] = ((unsigned)gy < (unsigned)HH && (unsigned)gx < (unsigned)WW)
                         ? (c * HWSZ + gy * WW + gx) : -1;
        } else {
            dstu[s] = 0; src[s] = -2;
        }
    }

    auto stage = [&](int cc, int b) {
        const float* ibase = in + cc * HWSZ;
        uint32_t ioff = (uint32_t)(b * SIN_F * 4);
#pragma unroll
        for (int s = 0; s < 9; ++s) {
            if (src[s] != -2) {
                int sz = (src[s] >= 0) ? 4 : 0;
                const float* sp = ibase + (src[s] >= 0 ? src[s] : 0);
                asm volatile("cp.async.ca.shared.global [%0], [%1], 4, %2;"
                             :: "r"(dstu[s] + ioff), "l"(sp), "r"(sz));
            }
        }
        const float4* wsrc = (const float4*)(wT + cc * 576);
        uint32_t woff = w_base + (uint32_t)(b * SW_F * 4);
#pragma unroll
        for (int s = 0; s < 5; ++s) {
            int idx = tid + s * 256;
            if (idx < 1152) {
                asm volatile("cp.async.cg.shared.global [%0], [%1], 16;"
                             :: "r"(woff + idx * 16), "l"(wsrc + idx));
            }
        }
        asm volatile("cp.async.commit_group;" ::: "memory");
    };

    unsigned long long acc2[4][4];
#pragma unroll
    for (int o = 0; o < 4; ++o)
#pragma unroll
        for (int j = 0; j < 4; ++j) acc2[o][j] = 0ull;

    constexpr int NCHUNK = CIN / 8;
    stage(0, 0);

    for (int ci = 0; ci < NCHUNK; ++ci) {
        asm volatile("cp.async.wait_group 0;" ::: "memory");
        __syncthreads();
        if (ci + 1 < NCHUNK) stage((ci + 1) * 8, (ci + 1) & 1);

        const float* s_in = s_in0 + (ci & 1) * SIN_F;
        const float* s_w = s_w0 + (ci & 1) * SW_F;
#pragma unroll
        for (int cl = 0; cl < 8; ++cl) {
#pragma unroll
            for (int dy = 0; dy < 3; ++dy) {
                const float* rowp = &s_in[cl * 272 + (ty + dy) * 68 + gx4];
                float4 a = *(const float4*)rowp;
                float2 b = *(const float2*)(rowp + 4);
                unsigned long long riv[6];
                riv[0] = packdup(a.x); riv[1] = packdup(a.y);
                riv[2] = packdup(a.z); riv[3] = packdup(a.w);
                riv[4] = packdup(b.x); riv[5] = packdup(b.y);
#pragma unroll
                for (int dx = 0; dx < 3; ++dx) {
                    const unsigned long long* wp = (const unsigned long long*)
                        &s_w[cl * 576 + (dy * 3 + dx) * 64 + (ob << 3)];
                    unsigned long long w0 = wp[0], w1 = wp[1], w2 = wp[2], w3 = wp[3];
#pragma unroll
                    for (int j = 0; j < 4; ++j) {
                        unsigned long long iv = riv[j + dx];
                        ffma2(acc2[0][j], w0, iv);
                        ffma2(acc2[1][j], w1, iv);
                        ffma2(acc2[2][j], w2, iv);
                        ffma2(acc2[3][j], w3, iv);
                    }
                }
            }
        }
    }
    int oy = by + ty;
    if (oy < HH) {
#pragma unroll
        for (int op = 0; op < 4; ++op) {
#pragma unroll
            for (int h = 0; h < 2; ++h) {
                int oc = (ob << 3) + op * 2 + h;
                float sc = s_scale[oc], sh = s_shift[oc];
                int base = oc * HWSZ + oy * WW + bx + gx4;
#pragma unroll
                for (int j = 0; j < 4; ++j) {
                    int ox = bx + gx4 + j;
                    if (ox < WW) {
                        float lo, hi;
                        unpack2(acc2[op][j], lo, hi);
                        float a = h ? hi : lo;
                        out[base + j] = fmaxf(fmaf(a, sc, sh), 0.f);
                    }
                }
            }
        }
    }
}

// ---------------- hm final conv (64->3) + bias + sigmoid, 4-row y-tile -----
__global__ void __launch_bounds__(128)
conv_hm_final(const float* __restrict__ h, const float* __restrict__ b2s) {
    __shared__ float s_in[8][6][132];
    __shared__ float s_w[64 * 27];
    int tid = threadIdx.x;
    int bx = blockIdx.x * 128, by = blockIdx.y * 4;
    for (int i = tid; i < 1728; i += 128) s_w[i] = g_w2hmT[i];
    float acc[3][4];
#pragma unroll
    for (int o = 0; o < 3; ++o)
#pragma unroll
        for (int y = 0; y < 4; ++y) acc[o][y] = 0.f;

    for (int cc = 0; cc < 64; cc += 8) {
        __syncthreads();
        for (int i = tid; i < 8 * 6 * 130; i += 128) {
            int c = i / 780, r = (i / 130) % 6, xx = i % 130;
            int gy = by + r - 1, gx = bx + xx - 1;
            float v = 0.f;
            if ((unsigned)gy < (unsigned)HH && (unsigned)gx < (unsigned)WW)
                v = h[(cc + c) * HWSZ + gy * WW + gx];
            s_in[c][r][xx] = v;
        }
        __syncthreads();
#pragma unroll
        for (int cl = 0; cl < 8; ++cl) {
            float col[6][3];
#pragma unroll
            for (int r = 0; r < 6; ++r)
#pragma unroll
                for (int dx = 0; dx < 3; ++dx) col[r][dx] = s_in[cl][r][tid + dx];
#pragma unroll
            for (int dy = 0; dy < 3; ++dy)
#pragma unroll
                for (int dx = 0; dx < 3; ++dx) {
                    const float* wp = &s_w[(cc + cl) * 27 + (dy * 3 + dx) * 3];
                    float w0 = wp[0], w1 = wp[1], w2 = wp[2];
#pragma unroll
                    for (int y = 0; y < 4; ++y) {
                        float iv = col[y + dy][dx];
                        acc[0][y] = fmaf(w0, iv, acc[0][y]);
                        acc[1][y] = fmaf(w1, iv, acc[1][y]);
                        acc[2][y] = fmaf(w2, iv, acc[2][y]);
                    }
                }
        }
    }
    int ox = bx + tid;
    if (ox < WW) {
#pragma unroll
        for (int y = 0; y < 4; ++y) {
            int oy = by + y;
            float v0 = acc[0][y] + b2s[0];
            float v1 = acc[1][y] + b2s[1];
            float v2 = acc[2][y] + b2s[2];
            g_hm[0 * HWSZ + oy * WW + ox] = 1.f / (1.f + expf(-v0));
            g_hm[1 * HWSZ + oy * WW + ox] = 1.f / (1.f + expf(-v1));
            g_hm[2 * HWSZ + oy * WW + ox] = 1.f / (1.f + expf(-v2));
        }
    }
}

// ---------------- top-k: privatized histograms / scans / collect / sort ----
__global__ void __launch_bounds__(1024) histA_kernel() {
    __shared__ unsigned sh[1024];
    int tid = threadIdx.x;
    sh[tid] = 0u;
    __syncthreads();
    int n = 3 * HWSZ;
    for (int i = blockIdx.x * blockDim.x + tid; i < n;
         i += gridDim.x * blockDim.x) {
        unsigned bits = __float_as_uint(g_hm[i]);
        atomicAdd(&sh[bits >> 22], 1u);
    }
    __syncthreads();
    unsigned v = sh[tid];
    if (v) atomicAdd(&g_histC[tid], v);
}

__global__ void scanA_kernel() {
    __shared__ unsigned s[1024];
    int tid = threadIdx.x;
    s[tid] = g_histC[tid];
    __syncthreads();
    if (tid == 0) {
        unsigned cum = 0;
        unsigned bc = 0, above = 0;
        for (int b = 1023; b >= 0; --b) {
            unsigned nc = cum + s[b];
            if (nc >= TOPK) { bc = (unsigned)b; above = cum; break; }
            cum = nc;
        }
        g_coarseSel = bc;
        g_aboveC = above;
    }
}

__global__ void __launch_bounds__(1024) histB_kernel() {
    __shared__ unsigned sh[1024];
    int tid = threadIdx.x;
    sh[tid] = 0u;
    __syncthreads();
    unsigned cb = g_coarseSel;
    int n = 3 * HWSZ;
    for (int i = blockIdx.x * blockDim.x + tid; i < n;
         i += gridDim.x * blockDim.x) {
        unsigned bits = __float_as_uint(g_hm[i]);
        if ((bits >> 22) == cb) atomicAdd(&sh[(bits >> 12) & 1023], 1u);
    }
    __syncthreads();
    unsigned v = sh[tid];
    if (v) atomicAdd(&g_histF[tid], v);
}

__global__ void scanB_kernel() {
    __shared__ unsigned s[1024];
    int tid = threadIdx.x;
    s[tid] = g_histF[tid];
    __syncthreads();
    if (tid == 0) {
        unsigned cb = g_coarseSel;
        unsigned cum = g_aboveC;
        unsigned th = 0;
        for (int t = 1023; t >= 0; --t) {
            cum += s[t];
            if (cum >= TOPK) { th = ((cb << 10) + (unsigned)t) << 12; break; }
        }
        g_thresh = th;
    }
}

__global__ void collect_kernel() {
    int n = 3 * HWSZ;
    unsigned th = g_thresh;
    for (int i = blockIdx.x * blockDim.x + threadIdx.x; i < n;
         i += gridDim.x * blockDim.x) {
        unsigned bits = __float_as_uint(g_hm[i]);
        if (bits >= th) {
            int slot = atomicAdd(&g_candCount, 1);
            if (slot < 4096)
                g_cand[slot] = ((unsigned long long)bits << 32) |
                               (unsigned)(0xFFFFFFFFu - (unsigned)i);
        }
    }
}

__global__ void __launch_bounds__(1024) sort_kernel() {
    __shared__ unsigned long long ks[4096];
    int tid = threadIdx.x;
    int n = g_candCount;
    if (n > 4096) n = 4096;
    int M = (n <= 1024) ? 1024 : 4096;   // adaptive size (count-dependent, deterministic)
    for (int i = tid; i < M; i += 1024) ks[i] = (i < n) ? g_cand[i] : 0ull;
    __syncthreads();
    for (int k = 2; k <= M; k <<= 1) {
        for (int j = k >> 1; j > 0; j >>= 1) {
            for (int i = tid; i < M; i += 1024) {
                int ixj = i ^ j;
                if (ixj > i) {
                    bool up = ((i & k) == 0);
                    unsigned long long a = ks[i], b = ks[ixj];
                    if ((a > b) == up) { ks[i] = b; ks[ixj] = a; }
                }
            }
            __syncthreads();
        }
    }
    if (tid < TOPK) {
        unsigned long long key = ks[M - 1 - tid];
        unsigned bits = (unsigned)(key >> 32);
        unsigned idx = 0xFFFFFFFFu - (unsigned)(key & 0xFFFFFFFFu);
        g_topk_score[tid] = __uint_as_float(bits);
        int cls = idx / HWSZ;
        int sp = idx - cls * HWSZ;
        g_topk_cls[tid] = cls;
        g_topk_sp[tid] = sp;
    }
}

// ---------------- sparse branch eval at top-k positions (f32x2) ----------
// grid: (125, 5); 128 threads: pos = tid>>5 (4 pos), oc-pair = tid&31.
// patch stored DUPLICATED in smem: all lanes read same addr (broadcast) ->
// LDS.64 yields ready f32x2 broadcast operand, zero MOVs.
constexpr int SPARSE_SMEM = (12800 + 4608 + 128) * 4;   // 70144 bytes

__global__ void __launch_bounds__(128)
sparse_kernel(const float* __restrict__ bn1s, const float* __restrict__ W2s,
              const float* __restrict__ b2s) {
    extern __shared__ float ss[];
    float* s_patch = ss;                 // [4][64][25] as f32x2 dup = 12800 floats
    float* s_w = ss + 12800;             // [8][9][64] (reused as s_h [4][9][64])
    float* s_bn = ss + 12800 + 4608;     // scale[64], shift[64]
    float* s_h = s_w;
    __shared__ int s_cx[4], s_cy[4];

    int tid = threadIdx.x;
    int bi = blockIdx.y;        // 0..4 -> branch bi+1
    int pg = blockIdx.x;        // 0..124
    int pos = tid >> 5, ocp = tid & 31, oc0 = ocp * 2;

    if (tid < 4) {
        int sp = g_topk_sp[pg * 4 + tid];
        s_cy[tid] = sp / WW;
        s_cx[tid] = sp % WW;
    }
    if (tid < 64) {
        const float* bp = bn1s + (bi + 1) * 256;
        float g = bp[tid], b = bp[64 + tid], m = bp[128 + tid], v = bp[192 + tid];
        float sc = g * rsqrtf(v + 1e-5f);
        s_bn[tid] = sc;
        s_bn[64 + tid] = b - m * sc;
    }
    __syncthreads();
    for (int i = tid; i < 6400; i += 128) {
        int p = i / 1600, rem = i % 1600;
        int c = rem / 25, rc = rem % 25, dy = rc / 5, dx = rc % 5;
        int gy = s_cy[p] + dy - 2, gx = s_cx[p] + dx - 2;
        float v = 0.f;
        if ((unsigned)gy < (unsigned)HH && (unsigned)gx < (unsigned)WW)
            v = g_shared[c * HWSZ + gy * WW + gx];
        ((float2*)s_patch)[i] = make_float2(v, v);
    }

    unsigned long long acc2[9];
#pragma unroll
    for (int q = 0; q < 9; ++q) acc2[q] = 0ull;

    const float* wsrc = g_w1bT + bi * 36864;
    for (int cc = 0; cc < 64; cc += 8) {
        __syncthreads();
        for (int i = tid; i < 4608; i += 128) s_w[i] = wsrc[cc * 576 + i];
        __syncthreads();
#pragma unroll
        for (int cl = 0; cl < 8; ++cl) {
            const unsigned long long* pd =
                (const unsigned long long*)s_patch + pos * 1600 + (cc + cl) * 25;
            unsigned long long pv[25];
#pragma unroll
            for (int q = 0; q < 25; ++q) pv[q] = pd[q];
#pragma unroll
            for (int dy = 0; dy < 3; ++dy)
#pragma unroll
                for (int dx = 0; dx < 3; ++dx) {
                    unsigned long long w = *(const unsigned long long*)
                        &s_w[cl * 576 + (dy * 3 + dx) * 64 + oc0];
#pragma unroll
                    for (int py = 0; py < 3; ++py)
#pragma unroll
                        for (int px = 0; px < 3; ++px)
                            ffma2(acc2[py * 3 + px], w, pv[(py + dy) * 5 + (px + dx)]);
                }
        }
    }
    __syncthreads();
    // BN + ReLU + SAME-padding validity; write h for both oc of the pair
    float sc0 = s_bn[oc0], sh0 = s_bn[64 + oc0];
    float sc1 = s_bn[oc0 + 1], sh1 = s_bn[64 + oc0 + 1];
#pragma unroll
    for (int px = 0; px < 9; ++px) {
        int py = px / 3, pxx = px % 3;
        int gy = s_cy[pos] + py - 1, gx = s_cx[pos] + pxx - 1;
        bool ok = ((unsigned)gy < (unsigned)HH && (unsigned)gx < (unsigned)WW);
        float lo, hi;
        unpack2(acc2[px], lo, hi);
        float h0 = ok ? fmaxf(fmaf(lo, sc0, sh0), 0.f) : 0.f;
        float h1 = ok ? fmaxf(fmaf(hi, sc1, sh1), 0.f) : 0.f;
        s_h[(pos * 9 + px) * 64 + oc0] = h0;
        s_h[(pos * 9 + px) * 64 + oc0 + 1] = h1;
    }
    __syncthreads();
    // final 3x3 conv at the center pixel, 4 pos x 3 outch = 12 sums, 4 warps
    int wid = tid >> 5, lane = tid & 31;
    for (int t = wid; t < 12; t += 4) {
        int p = t / 3, o2 = t % 3;
        const float* w2 = W2s + (((bi + 1) * 3 + o2) * 64) * 9;
        float sum = 0.f;
        for (int i = lane; i < 576; i += 32) {
            int ic = i & 63, tp = i >> 6;
            sum = fmaf(s_h[(p * 9 + tp) * 64 + ic], w2[ic * 9 + tp], sum);
        }
#pragma unroll
        for (int off = 16; off > 0; off >>= 1)
            sum += __shfl_down_sync(0xffffffff, sum, off);
        if (lane == 0)
            g_sparse[(bi * 512 + pg * 4 + p) * 3 + o2] = sum + b2s[(bi + 1) * 3 + o2];
    }
}

// ---------------- decode ----------------
__global__ void decode_kernel(float* __restrict__ out) {
    int k = threadIdx.x;
    if (k >= TOPK) return;
    const float rect[3] = {0.68f, 0.71f, 0.65f};
    float s = g_topk_score[k];
    int cls = g_topk_cls[k];
    int sp = g_topk_sp[k];
    float ys = (float)(sp / WW);
    float xs = (float)(sp % WW);
    float c0 = g_sparse[(0 * 512 + k) * 3 + 0];
    float c1 = g_sparse[(0 * 512 + k) * 3 + 1];
    float cz = g_sparse[(1 * 512 + k) * 3 + 0];
    float d0 = expf(g_sparse[(2 * 512 + k) * 3 + 0]);
    float d1 = expf(g_sparse[(2 * 512 + k) * 3 + 1]);
    float d2 = expf(g_sparse[(2 * 512 + k) * 3 + 2]);
    float r0 = g_sparse[(3 * 512 + k) * 3 + 0];
    float r1 = g_sparse[(3 * 512 + k) * 3 + 1];
    float io = g_sparse[(4 * 512 + k) * 3 + 0];

    float xg = fmaf(xs + c0, 0.4f, -75.2f);
    float yg = fmaf(ys + c1, 0.4f, -75.2f);
    float heading = atan2f(r1, r0);
    io = fminf(fmaxf((io + 1.f) * 0.5f, 0.f), 1.f);
    float r = rect[cls];
    float sc = powf(s, 1.f - r) * powf(io, r);
    sc = (sc > 0.1f) ? sc : 0.f;

    out[k * 7 + 0] = xg;
    out[k * 7 + 1] = yg;
    out[k * 7 + 2] = cz;
    out[k * 7 + 3] = d0;
    out[k * 7 + 4] = d1;
    out[k * 7 + 5] = d2;
    out[k * 7 + 6] = heading;
    out[7 * TOPK + k] = sc;
    out[8 * TOPK + k] = (float)cls;
}

// ---------------- launch ----------------
extern "C" void kernel_launch(void* const* d_in, const int* in_sizes, int n_in,
                              void* d_out, int out_size) {
    const float* x = (const float*)d_in[0];
    const float* W_sh = (const float*)d_in[1];
    const float* bn_sh = (const float*)d_in[2];
    const float* W1s = (const float*)d_in[3];
    const float* bn1s = (const float*)d_in[4];
    const float* W2s = (const float*)d_in[5];
    const float* b2s = (const float*)d_in[6];
    float* out = (float*)d_out;

    float *p_shared, *p_h0, *p_wshT, *p_w1hmT;
    cudaGetSymbolAddress((void**)&p_shared, g_shared);
    cudaGetSymbolAddress((void**)&p_h0, g_h0);
    cudaGetSymbolAddress((void**)&p_wshT, g_wshT);
    cudaGetSymbolAddress((void**)&p_w1hmT, g_w1hmT);

    static bool attr_done = false;
    if (!attr_done) {
        cudaFuncSetAttribute(conv3x3_bn_relu<256>,
                             cudaFuncAttributeMaxDynamicSharedMemorySize, DYN_SMEM);
        cudaFuncSetAttribute(conv3x3_bn_relu<64>,
                             cudaFuncAttributeMaxDynamicSharedMemorySize, DYN_SMEM);
        cudaFuncSetAttribute(sparse_kernel,
                             cudaFuncAttributeMaxDynamicSharedMemorySize, SPARSE_SMEM);
        attr_done = true;
    }

    prep_kernel<<<512, 256>>>(W_sh, W1s, W2s);
    memset_kernel<<<1, 1024>>>();

    dim3 cg((WW + 63) / 64, (HH + 1) / 2);
    conv3x3_bn_relu<256><<<cg, 256, DYN_SMEM>>>(x, p_wshT, bn_sh, p_shared);
    conv3x3_bn_relu<64><<<cg, 256, DYN_SMEM>>>(p_shared, p_w1hmT, bn1s, p_h0);

    dim3 hg((WW + 127) / 128, (HH + 3) / 4);
    conv_hm_final<<<hg, 128>>>(p_h0, b2s);

    histA_kernel<<<148, 1024>>>();
    scanA_kernel<<<1, 1024>>>();
    histB_kernel<<<148, 1024>>>();
    scanB_kernel<<<1, 1024>>>();
    collect_kernel<<<829, 512>>>();
    sort_kernel<<<1, 1024>>>();

    sparse_kernel<<<dim3(125, 5), 128, SPARSE_SMEM>>>(bn1s, W2s, b2s);
    decode_kernel<<<1, 512>>>(out);
}